// round 3
// baseline (speedup 1.0000x reference)
#include <cuda_runtime.h>

#define TCOLS 4096
#define BROWS 4096
#define NT 512
#define NW (NT / 32)

__device__ float    g_partials[BROWS];
__device__ unsigned g_done;   // zero-init; reset by last block each launch

__device__ __forceinline__ float warp_sum(float v) {
    #pragma unroll
    for (int o = 16; o; o >>= 1) v += __shfl_xor_sync(0xffffffffu, v, o);
    return v;
}

template <int N>
__device__ __forceinline__ void block_reduce(float* vals, float* red, int tid) {
    const int lane = tid & 31;
    const int wid  = tid >> 5;
    #pragma unroll
    for (int k = 0; k < N; k++) {
        float v = warp_sum(vals[k]);
        if (lane == 0) red[k * NW + wid] = v;
    }
    __syncthreads();
    #pragma unroll
    for (int k = 0; k < N; k++) {
        float s = 0.f;
        #pragma unroll
        for (int w = 0; w < NW; w++) s += red[k * NW + w];
        vals[k] = s;
    }
    __syncthreads();
}

__global__ __launch_bounds__(NT, 3)
void pv_fused_kernel(const float* __restrict__ preds,
                     const float* __restrict__ labels,
                     float* __restrict__ out) {
    __shared__ float red[8 * NW];
    __shared__ bool  amLast;

    const int row  = blockIdx.x;
    const int tid  = threadIdx.x;
    const int lane = tid & 31;
    const int wid  = tid >> 5;
    const int warpBase = wid * 256;   // contiguous 256 elements per warp

    const float* rp = preds  + (size_t)row * TCOLS;
    const float* rl = labels + (size_t)row * TCOLS;

    // Coalesced loads: group 0 = elems warpBase+4*lane.., group 1 = +128
    float vp[8], vl[8];
    {
        const float4* gp = (const float4*)(rp + warpBase);
        const float4* gl = (const float4*)(rl + warpBase);
        float4 a0 = gp[lane], a1 = gp[32 + lane];
        vp[0] = a0.x; vp[1] = a0.y; vp[2] = a0.z; vp[3] = a0.w;
        vp[4] = a1.x; vp[5] = a1.y; vp[6] = a1.z; vp[7] = a1.w;
        float4 b0 = gl[lane], b1 = gl[32 + lane];
        vl[0] = b0.x; vl[1] = b0.y; vl[2] = b0.z; vl[3] = b0.w;
        vl[4] = b1.x; vl[5] = b1.y; vl[6] = b1.z; vl[7] = b1.w;
    }

    // Warp-edge neighbors; NaN at row edges kills peak/valley tests for free.
    const float NANF = __int_as_float(0x7fffffff);
    float wlp = NANF, wll = NANF, wrp = NANF, wrl = NANF;
    if (lane == 0 && warpBase > 0) {
        wlp = rp[warpBase - 1];
        wll = rl[warpBase - 1];
    }
    if (lane == 31 && warpBase + 256 < TCOLS) {
        wrp = rp[warpBase + 256];
        wrl = rl[warpBase + 256];
    }

    // ---- Pass 1: peak/valley sums, counts, masks (shuffle-stitched windows) ----
    float acc[8];
    #pragma unroll
    for (int k = 0; k < 8; k++) acc[k] = 0.f;

    auto detect = [&](const float* v, float wl, float wr,
                      float& psum, float& pcnt, float& vsum, float& vcnt) -> unsigned {
        unsigned mask = 0;
        float carry = __shfl_sync(0xffffffffu, v[3], 31);  // group0 last elem
        float lead  = __shfl_sync(0xffffffffu, v[4], 0);   // group1 first elem
        #pragma unroll
        for (int g = 0; g < 2; g++) {
            float lv = __shfl_up_sync(0xffffffffu, v[4 * g + 3], 1);
            if (lane == 0)  lv = (g == 0) ? wl : carry;
            float rv = __shfl_down_sync(0xffffffffu, v[4 * g], 1);
            if (lane == 31) rv = (g == 0) ? lead : wr;

            float d[5];
            d[0] = v[4 * g] - lv;
            d[1] = v[4 * g + 1] - v[4 * g];
            d[2] = v[4 * g + 2] - v[4 * g + 1];
            d[3] = v[4 * g + 3] - v[4 * g + 2];
            d[4] = rv - v[4 * g + 3];
            #pragma unroll
            for (int k = 0; k < 4; k++) {
                bool pk = (d[k] > 0.f) & (d[k + 1] < 0.f);
                bool vy = (d[k] < 0.f) & (d[k + 1] > 0.f);
                float b = v[4 * g + k];
                if (pk) { psum += b; pcnt += 1.f; mask |= 1u << (4 * g + k); }
                if (vy) { vsum += b; vcnt += 1.f; mask |= 1u << (8 + 4 * g + k); }
            }
        }
        return mask;
    };

    unsigned mp = detect(vp, wlp, wrp, acc[0], acc[1], acc[2], acc[3]);
    unsigned ml = detect(vl, wll, wrl, acc[4], acc[5], acc[6], acc[7]);

    block_reduce<8>(acc, red, tid);

    const float pmean_p = acc[0] / acc[1];
    const float vmean_p = acc[2] / acc[3];
    const float pmean_l = acc[4] / acc[5];
    const float vmean_l = acc[6] / acc[7];

    // ---- Pass 2: thresholded masked means from registers ----
    float s[8];
    #pragma unroll
    for (int k = 0; k < 8; k++) s[k] = 0.f;

    #pragma unroll
    for (int k = 0; k < 8; k++) {
        const float bp = vp[k];
        if (((mp >> k) & 1u)       && bp >= pmean_p) { s[0] += bp; s[1] += 1.f; }
        if (((mp >> (8 + k)) & 1u) && bp <= vmean_p) { s[2] += bp; s[3] += 1.f; }
        const float bl = vl[k];
        if (((ml >> k) & 1u)       && bl >= pmean_l) { s[4] += bl; s[5] += 1.f; }
        if (((ml >> (8 + k)) & 1u) && bl <= vmean_l) { s[6] += bl; s[7] += 1.f; }
    }
    block_reduce<8>(s, red, tid);

    if (tid == 0) {
        float sbp_p = s[0] / s[1];
        float dbp_p = s[2] / s[3];
        float sbp_l = s[4] / s[5];
        float dbp_l = s[6] / s[7];
        float d0 = sbp_p - sbp_l;
        float d1 = dbp_p - dbp_l;
        g_partials[row] = d0 * d0 + d1 * d1;
        __threadfence();
        unsigned c = atomicAdd(&g_done, 1u);
        amLast = (c == (unsigned)(gridDim.x - 1));
    }
    __syncthreads();

    // ---- Last block reduces all per-row partials ----
    if (amLast) {
        float v = 0.f;
        #pragma unroll
        for (int q = 0; q < BROWS / NT; q++) v += g_partials[tid + q * NT];
        v = warp_sum(v);
        if (lane == 0) red[wid] = v;
        __syncthreads();
        if (tid == 0) {
            float t = 0.f;
            #pragma unroll
            for (int w = 0; w < NW; w++) t += red[w];
            out[0] = t / (float)(BROWS * 2);
            g_done = 0;
        }
    }
}

extern "C" void kernel_launch(void* const* d_in, const int* in_sizes, int n_in,
                              void* d_out, int out_size) {
    const float* preds  = (const float*)d_in[0];
    const float* labels = (const float*)d_in[1];
    pv_fused_kernel<<<BROWS, NT>>>(preds, labels, (float*)d_out);
}

// round 4
// speedup vs baseline: 2.0404x; 2.0404x over previous
#include <cuda_runtime.h>

#define TCOLS 4096
#define BROWS 4096
#define NT 256
#define NW 8            // warps per block
#define WELEM 512       // elements owned per warp
#define NG 4            // float4 groups per lane per array
#define FULL 0xffffffffu

__device__ float    g_partials[BROWS];
__device__ unsigned g_done;   // zero-init; reset by last block

__device__ __forceinline__ float warp_sum(float v) {
    #pragma unroll
    for (int o = 16; o; o >>= 1) v += __shfl_xor_sync(FULL, v, o);
    return v;
}

// Reduce 4 float sums + 4 int counts block-wide; broadcast all 8 (counts as
// float) into out[8]. redf must hold >= 72 floats.
__device__ __forceinline__ void block_reduce8(float s[4], unsigned c[4],
                                              float out[8], float* redf,
                                              int lane, int wid) {
    #pragma unroll
    for (int j = 0; j < 4; j++) s[j] = warp_sum(s[j]);
    #pragma unroll
    for (int j = 0; j < 4; j++) c[j] = __reduce_add_sync(FULL, c[j]);
    if (lane == 0) {
        #pragma unroll
        for (int j = 0; j < 4; j++) {
            redf[j * NW + wid]       = s[j];
            redf[(4 + j) * NW + wid] = (float)c[j];
        }
    }
    __syncthreads();
    // 8 warps each reduce one of the 8 values over NW=8 partials
    float v = (lane < NW) ? redf[wid * NW + lane] : 0.f;
    v += __shfl_xor_sync(FULL, v, 4);
    v += __shfl_xor_sync(FULL, v, 2);
    v += __shfl_xor_sync(FULL, v, 1);
    if (lane == 0) redf[64 + wid] = v;
    __syncthreads();
    #pragma unroll
    for (int j = 0; j < 8; j++) out[j] = redf[64 + j];
    __syncthreads();   // redf free for next use
}

// Peak/valley detect over this lane's 16 elements (4 float4 groups).
// Returns 16-bit peak mask / valley mask; accumulates peak/valley value sums.
__device__ __forceinline__ void detect(const float v[16], float wl, float wr,
                                       int lane,
                                       unsigned& pkm, unsigned& vym,
                                       float& psum, float& vsum) {
    float last_b[NG], first_b[NG];
    #pragma unroll
    for (int g = 0; g < NG; g++) {
        last_b[g]  = __shfl_sync(FULL, v[4 * g + 3], 31);
        first_b[g] = __shfl_sync(FULL, v[4 * g], 0);
    }
    pkm = 0; vym = 0; psum = 0.f; vsum = 0.f;
    #pragma unroll
    for (int g = 0; g < NG; g++) {
        float lv = __shfl_up_sync(FULL, v[4 * g + 3], 1);
        if (lane == 0)  lv = (g == 0) ? wl : last_b[g - 1];
        float rv = __shfl_down_sync(FULL, v[4 * g], 1);
        if (lane == 31) rv = (g == NG - 1) ? wr : first_b[g + 1];

        float d[5];
        d[0] = v[4 * g] - lv;
        d[1] = v[4 * g + 1] - v[4 * g];
        d[2] = v[4 * g + 2] - v[4 * g + 1];
        d[3] = v[4 * g + 3] - v[4 * g + 2];
        d[4] = rv - v[4 * g + 3];
        #pragma unroll
        for (int k = 0; k < 4; k++) {
            bool pk = (d[k] > 0.f) & (d[k + 1] < 0.f);
            bool vy = (d[k] < 0.f) & (d[k + 1] > 0.f);
            float b = v[4 * g + k];
            if (pk) { psum += b; pkm |= 1u << (4 * g + k); }
            if (vy) { vsum += b; vym |= 1u << (4 * g + k); }
        }
    }
}

__global__ __launch_bounds__(NT)
void pv_fused_kernel(const float* __restrict__ preds,
                     const float* __restrict__ labels,
                     float* __restrict__ out) {
    __shared__ float red[72];
    __shared__ bool  amLast;

    const int row  = blockIdx.x;
    const int tid  = threadIdx.x;
    const int lane = tid & 31;
    const int wid  = tid >> 5;
    const int wb   = wid * WELEM;

    const float* rp = preds  + (size_t)row * TCOLS;
    const float* rl = labels + (size_t)row * TCOLS;

    // Coalesced loads: lane's group g = elements wb + g*128 + 4*lane .. +3
    float vp[16], vl[16];
    {
        const float4* gp = (const float4*)(rp + wb);
        const float4* gl = (const float4*)(rl + wb);
        #pragma unroll
        for (int g = 0; g < NG; g++) {
            float4 a = gp[g * 32 + lane];
            vp[4 * g] = a.x; vp[4 * g + 1] = a.y; vp[4 * g + 2] = a.z; vp[4 * g + 3] = a.w;
            float4 b = gl[g * 32 + lane];
            vl[4 * g] = b.x; vl[4 * g + 1] = b.y; vl[4 * g + 2] = b.z; vl[4 * g + 3] = b.w;
        }
    }

    // Warp-edge neighbors; NaN at row edges excludes positions 0 / TCOLS-1.
    const float NANF = __int_as_float(0x7fffffff);
    float wlp = NANF, wll = NANF, wrp = NANF, wrl = NANF;
    if (lane == 0 && wb > 0)                { wlp = rp[wb - 1];     wll = rl[wb - 1]; }
    if (lane == 31 && wb + WELEM < TCOLS)   { wrp = rp[wb + WELEM]; wrl = rl[wb + WELEM]; }

    // ---- Pass 1: detect + means ----
    unsigned pkm_p, vym_p, pkm_l, vym_l;
    float s1[4];
    unsigned c1[4];
    detect(vp, wlp, wrp, lane, pkm_p, vym_p, s1[0], s1[1]);
    detect(vl, wll, wrl, lane, pkm_l, vym_l, s1[2], s1[3]);
    c1[0] = __popc(pkm_p); c1[1] = __popc(vym_p);
    c1[2] = __popc(pkm_l); c1[3] = __popc(vym_l);

    float o1[8];
    block_reduce8(s1, c1, o1, red, lane, wid);
    const float pmean_p = o1[0] / o1[4];
    const float vmean_p = o1[1] / o1[5];
    const float pmean_l = o1[2] / o1[6];
    const float vmean_l = o1[3] / o1[7];

    // ---- Pass 2: thresholded masked means ----
    float s2[4] = {0.f, 0.f, 0.f, 0.f};
    unsigned c2[4] = {0u, 0u, 0u, 0u};
    #pragma unroll
    for (int k = 0; k < 16; k++) {
        const float bp = vp[k];
        if (((pkm_p >> k) & 1u) && bp >= pmean_p) { s2[0] += bp; c2[0]++; }
        if (((vym_p >> k) & 1u) && bp <= vmean_p) { s2[1] += bp; c2[1]++; }
        const float bl = vl[k];
        if (((pkm_l >> k) & 1u) && bl >= pmean_l) { s2[2] += bl; c2[2]++; }
        if (((vym_l >> k) & 1u) && bl <= vmean_l) { s2[3] += bl; c2[3]++; }
    }

    float o2[8];
    block_reduce8(s2, c2, o2, red, lane, wid);

    if (tid == 0) {
        float sbp_p = o2[0] / o2[4];
        float dbp_p = o2[1] / o2[5];
        float sbp_l = o2[2] / o2[6];
        float dbp_l = o2[3] / o2[7];
        float d0 = sbp_p - sbp_l;
        float d1 = dbp_p - dbp_l;
        g_partials[row] = d0 * d0 + d1 * d1;
        __threadfence();
        unsigned c = atomicAdd(&g_done, 1u);
        amLast = (c == (unsigned)(gridDim.x - 1));
    }
    __syncthreads();

    // ---- Last block reduces all per-row partials ----
    if (amLast) {
        float v = 0.f;
        #pragma unroll
        for (int q = 0; q < BROWS / NT; q++) v += g_partials[tid + q * NT];
        v = warp_sum(v);
        if (lane == 0) red[wid] = v;
        __syncthreads();
        if (tid == 0) {
            float t = 0.f;
            #pragma unroll
            for (int w = 0; w < NW; w++) t += red[w];
            out[0] = t / (float)(BROWS * 2);
            g_done = 0;
        }
    }
}

extern "C" void kernel_launch(void* const* d_in, const int* in_sizes, int n_in,
                              void* d_out, int out_size) {
    const float* preds  = (const float*)d_in[0];
    const float* labels = (const float*)d_in[1];
    pv_fused_kernel<<<BROWS, NT>>>(preds, labels, (float*)d_out);
}